// round 8
// baseline (speedup 1.0000x reference)
#include <cuda_runtime.h>
#include <math_constants.h>

#define BATCH  8
#define NPTS   4096
#define TPB    32               // one warp per block
#define QPT    4                // queries per thread
#define QPB    (TPB * QPT)      // 128 queries per block
#define QTILES (NPTS / QPB)     // 32 query tiles per (dir,b)
#define SPLITS 4                // DB split factor
#define SLICE  (NPTS / SPLITS)  // 1024 DB points per block (16KB smem)
#define NQTOT  (2 * BATCH * NPTS)   // 65536 total queries (both dirs)

// partial min of expanded val, per DB-slice: [split][flat_query]
__device__ float g_pmin[SPLITS][NQTOT];
// per-block partial sums from combine kernel
#define CGRID 128
__device__ float g_bpart[CGRID];

// ---- f32x2 helpers -------------------------------------------------------
__device__ __forceinline__ unsigned long long pk(float lo, float hi) {
    unsigned long long r;
    asm("mov.b64 %0, {%1, %2};" : "=l"(r) : "f"(lo), "f"(hi));
    return r;
}
__device__ __forceinline__ unsigned long long fma2(unsigned long long a,
                                                   unsigned long long b,
                                                   unsigned long long c) {
    unsigned long long r;
    asm("fma.rn.f32x2 %0, %1, %2, %3;" : "=l"(r) : "l"(a), "l"(b), "l"(c));
    return r;
}
__device__ __forceinline__ void unpk(unsigned long long v, float& lo, float& hi) {
    asm("mov.b64 {%0, %1}, %2;" : "=f"(lo), "=f"(hi) : "l"(v));
}

// One block = one warp = 128 queries x 1024-point DB slice.
// grid = (QTILES*SPLITS, BATCH, 2). dir 0: queries=tar, DB=src ; dir 1: swapped.
__global__ __launch_bounds__(TPB)
void chamfer_kernel(const float* __restrict__ tar, const float* __restrict__ src) {
    const int dir   = blockIdx.z;
    const float* qraw = (dir == 0) ? tar : src;
    const float* draw = (dir == 0) ? src : tar;

    const int b     = blockIdx.y;
    const int tile  = blockIdx.x / SPLITS;
    const int split = blockIdx.x % SPLITS;
    const int tid   = threadIdx.x;

    // 4 queries per thread, warp-stride for coalescing
    unsigned long long qx2[QPT], qy2[QPT], qz2[QPT];
    #pragma unroll
    for (int k = 0; k < QPT; k++) {
        const int qi = tile * QPB + k * TPB + tid;
        const float* qp = qraw + (size_t)(b * NPTS + qi) * 3;
        float x = qp[0], y = qp[1], z = qp[2];
        qx2[k] = pk(x, x); qy2[k] = pk(y, y); qz2[k] = pk(z, z);
    }

    const float* dbb = draw + (size_t)(b * NPTS + split * SLICE) * 3;

    // pair-SoA smem: sA[j] = {pack(-2x0,-2x1), pack(-2y0,-2y1)}
    //                sB[j] = {pack(-2z0,-2z1), pack(|p0|^2,|p1|^2)}
    __shared__ ulonglong2 sA[SLICE / 2];
    __shared__ ulonglong2 sB[SLICE / 2];

    // fill + pack (single stage: whole slice fits)
    #pragma unroll 4
    for (int j = tid; j < SLICE / 2; j += TPB) {
        const float2* p2 = (const float2*)(dbb + (size_t)(2 * j) * 3);
        float2 v0 = p2[0], v1 = p2[1], v2 = p2[2];
        // point0 = (v0.x, v0.y, v1.x), point1 = (v1.y, v2.x, v2.y)
        float n0 = fmaf(v0.x, v0.x, fmaf(v0.y, v0.y, v1.x * v1.x));
        float n1 = fmaf(v1.y, v1.y, fmaf(v2.x, v2.x, v2.y * v2.y));
        sA[j] = make_ulonglong2(pk(-2.f * v0.x, -2.f * v1.y),
                                pk(-2.f * v0.y, -2.f * v2.x));
        sB[j] = make_ulonglong2(pk(-2.f * v1.x, -2.f * v2.y),
                                pk(n0, n1));
    }
    __syncthreads();

    float m0[QPT], m1[QPT], m2[QPT], m3[QPT];
    #pragma unroll
    for (int k = 0; k < QPT; k++) { m0[k] = m1[k] = m2[k] = m3[k] = CUDART_INF_F; }

    #pragma unroll 2
    for (int j = 0; j < SLICE / 2; j += 2) {
        ulonglong2 pa0 = sA[j + 0];
        ulonglong2 pb0 = sB[j + 0];
        ulonglong2 pa1 = sA[j + 1];
        ulonglong2 pb1 = sB[j + 1];

        #pragma unroll
        for (int k = 0; k < QPT; k++) {
            unsigned long long t = fma2(qz2[k], pb0.x, pb0.y);
            t = fma2(qy2[k], pa0.y, t);
            t = fma2(qx2[k], pa0.x, t);
            float lo, hi; unpk(t, lo, hi);
            m0[k] = fminf(m0[k], lo); m1[k] = fminf(m1[k], hi);

            t = fma2(qz2[k], pb1.x, pb1.y);
            t = fma2(qy2[k], pa1.y, t);
            t = fma2(qx2[k], pa1.x, t);
            unpk(t, lo, hi);
            m2[k] = fminf(m2[k], lo); m3[k] = fminf(m3[k], hi);
        }
    }

    // write per-(query, slice) partial min-val (coalesced per k)
    const int base = (dir * BATCH + b) * NPTS + tile * QPB;
    #pragma unroll
    for (int k = 0; k < QPT; k++) {
        float mn = fminf(fminf(m0[k], m1[k]), fminf(m2[k], m3[k]));
        g_pmin[split][base + k * TPB + tid] = mn;
    }
}

// Combine slices, add |q|^2, sqrt, and sum per block. grid=(CGRID), 256 thr, 2 queries/thread.
__global__ void combine_kernel(const float* __restrict__ tar, const float* __restrict__ src) {
    const int t = threadIdx.x;
    float acc = 0.f;
    #pragma unroll
    for (int u = 0; u < 2; u++) {
        const int fq  = blockIdx.x * 512 + u * 256 + t;   // flat query id
        const int dir = fq >> 15;                          // 32768 queries per dir
        const int rem = fq & 32767;                        // b*NPTS + qi
        const float* qraw = (dir == 0) ? tar : src;
        const float* qp = qraw + (size_t)rem * 3;
        const float x = qp[0], y = qp[1], z = qp[2];
        const float qn = fmaf(x, x, fmaf(y, y, z * z));

        float m = g_pmin[0][fq];
        #pragma unroll
        for (int s = 1; s < SPLITS; s++) m = fminf(m, g_pmin[s][fq]);
        acc += sqrtf(fmaxf(qn + m, 0.f));
    }

    #pragma unroll
    for (int o = 16; o > 0; o >>= 1)
        acc += __shfl_down_sync(0xffffffffu, acc, o);

    __shared__ float ws[8];
    if ((t & 31) == 0) ws[t >> 5] = acc;
    __syncthreads();
    if (t == 0) {
        float sblk = 0.f;
        #pragma unroll
        for (int i = 0; i < 8; i++) sblk += ws[i];
        g_bpart[blockIdx.x] = sblk;   // blocks [0,64) = dir0, [64,128) = dir1
    }
}

__global__ void finalize_kernel(float* __restrict__ out) {
    const int t = threadIdx.x;   // 128 threads
    float v = g_bpart[t];
    #pragma unroll
    for (int o = 16; o > 0; o >>= 1)
        v += __shfl_down_sync(0xffffffffu, v, o);

    __shared__ float ws[4];
    if ((t & 31) == 0) ws[t >> 5] = v;
    __syncthreads();
    if (t == 0) {
        const float inv = 1.f / (float)(BATCH * NPTS);
        float complete = (ws[0] + ws[1]) * inv;   // dir 0 (tar -> src)
        float accuracy = (ws[2] + ws[3]) * inv;   // dir 1 (src -> tar)
        out[0] = accuracy;
        out[1] = complete;
        out[2] = 0.5f * (accuracy + complete);
    }
}

extern "C" void kernel_launch(void* const* d_in, const int* in_sizes, int n_in,
                              void* d_out, int out_size) {
    const float* tar = (const float*)d_in[0];
    const float* src = (const float*)d_in[1];
    float* out = (float*)d_out;

    chamfer_kernel<<<dim3(QTILES * SPLITS, BATCH, 2), TPB>>>(tar, src);
    combine_kernel<<<CGRID, 256>>>(tar, src);
    finalize_kernel<<<1, 128>>>(out);
}

// round 9
// speedup vs baseline: 1.2875x; 1.2875x over previous
#include <cuda_runtime.h>
#include <math_constants.h>

#define BATCH  8
#define NPTS   4096
#define TPB    64               // two warps per block
#define QPT    4                // queries per thread
#define QPB    (TPB * QPT)      // 256 queries per block
#define QTILES (NPTS / QPB)     // 16 query tiles per (dir,b)
#define SPLITS 8                // DB split factor
#define SLICE  (NPTS / SPLITS)  // 512 DB points per block (8KB smem)
#define NQTOT  (2 * BATCH * NPTS)   // 65536 total queries (both dirs)

// partial min of expanded val, per DB-slice: [split][flat_query]
__device__ float g_pmin[SPLITS][NQTOT];
// per-block partial sums from combine kernel + completion counter
#define CGRID 128
__device__ float g_bpart[CGRID];
__device__ int   g_count;   // zero-init; last combine block resets to 0

// ---- f32x2 helpers -------------------------------------------------------
__device__ __forceinline__ unsigned long long pk(float lo, float hi) {
    unsigned long long r;
    asm("mov.b64 %0, {%1, %2};" : "=l"(r) : "f"(lo), "f"(hi));
    return r;
}
__device__ __forceinline__ unsigned long long fma2(unsigned long long a,
                                                   unsigned long long b,
                                                   unsigned long long c) {
    unsigned long long r;
    asm("fma.rn.f32x2 %0, %1, %2, %3;" : "=l"(r) : "l"(a), "l"(b), "l"(c));
    return r;
}
__device__ __forceinline__ void unpk(unsigned long long v, float& lo, float& hi) {
    asm("mov.b64 {%0, %1}, %2;" : "=f"(lo), "=f"(hi) : "l"(v));
}

// One block = 256 queries x 512-point DB slice.
// grid = (QTILES*SPLITS, BATCH, 2). dir 0: queries=tar, DB=src ; dir 1: swapped.
__global__ __launch_bounds__(TPB)
void chamfer_kernel(const float* __restrict__ tar, const float* __restrict__ src) {
    const int dir   = blockIdx.z;
    const float* qraw = (dir == 0) ? tar : src;
    const float* draw = (dir == 0) ? src : tar;

    const int b     = blockIdx.y;
    const int tile  = blockIdx.x / SPLITS;
    const int split = blockIdx.x % SPLITS;
    const int tid   = threadIdx.x;

    // 4 queries per thread, block-stride for coalescing
    unsigned long long qx2[QPT], qy2[QPT], qz2[QPT];
    #pragma unroll
    for (int k = 0; k < QPT; k++) {
        const int qi = tile * QPB + k * TPB + tid;
        const float* qp = qraw + (size_t)(b * NPTS + qi) * 3;
        float x = qp[0], y = qp[1], z = qp[2];
        qx2[k] = pk(x, x); qy2[k] = pk(y, y); qz2[k] = pk(z, z);
    }

    const float* dbb = draw + (size_t)(b * NPTS + split * SLICE) * 3;

    // pair-SoA smem: sA[j] = {pack(-2x0,-2x1), pack(-2y0,-2y1)}
    //                sB[j] = {pack(-2z0,-2z1), pack(|p0|^2,|p1|^2)}
    __shared__ ulonglong2 sA[SLICE / 2];
    __shared__ ulonglong2 sB[SLICE / 2];

    // fill + pack (whole slice fits; 2 warps cooperate)
    #pragma unroll 2
    for (int j = tid; j < SLICE / 2; j += TPB) {
        const float2* p2 = (const float2*)(dbb + (size_t)(2 * j) * 3);
        float2 v0 = p2[0], v1 = p2[1], v2 = p2[2];
        // point0 = (v0.x, v0.y, v1.x), point1 = (v1.y, v2.x, v2.y)
        float n0 = fmaf(v0.x, v0.x, fmaf(v0.y, v0.y, v1.x * v1.x));
        float n1 = fmaf(v1.y, v1.y, fmaf(v2.x, v2.x, v2.y * v2.y));
        sA[j] = make_ulonglong2(pk(-2.f * v0.x, -2.f * v1.y),
                                pk(-2.f * v0.y, -2.f * v2.x));
        sB[j] = make_ulonglong2(pk(-2.f * v1.x, -2.f * v2.y),
                                pk(n0, n1));
    }
    __syncthreads();

    float m0[QPT], m1[QPT], m2[QPT], m3[QPT];
    #pragma unroll
    for (int k = 0; k < QPT; k++) { m0[k] = m1[k] = m2[k] = m3[k] = CUDART_INF_F; }

    #pragma unroll 2
    for (int j = 0; j < SLICE / 2; j += 2) {
        ulonglong2 pa0 = sA[j + 0];
        ulonglong2 pb0 = sB[j + 0];
        ulonglong2 pa1 = sA[j + 1];
        ulonglong2 pb1 = sB[j + 1];

        #pragma unroll
        for (int k = 0; k < QPT; k++) {
            unsigned long long t = fma2(qz2[k], pb0.x, pb0.y);
            t = fma2(qy2[k], pa0.y, t);
            t = fma2(qx2[k], pa0.x, t);
            float lo, hi; unpk(t, lo, hi);
            m0[k] = fminf(m0[k], lo); m1[k] = fminf(m1[k], hi);

            t = fma2(qz2[k], pb1.x, pb1.y);
            t = fma2(qy2[k], pa1.y, t);
            t = fma2(qx2[k], pa1.x, t);
            unpk(t, lo, hi);
            m2[k] = fminf(m2[k], lo); m3[k] = fminf(m3[k], hi);
        }
    }

    // write per-(query, slice) partial min-val (coalesced per k)
    const int base = (dir * BATCH + b) * NPTS + tile * QPB;
    #pragma unroll
    for (int k = 0; k < QPT; k++) {
        float mn = fminf(fminf(m0[k], m1[k]), fminf(m2[k], m3[k]));
        g_pmin[split][base + k * TPB + tid] = mn;
    }
}

// Combine slices, add |q|^2, sqrt, sum; last block folds g_bpart -> out.
// grid=(CGRID), 256 threads, 2 queries/thread.
__global__ void combine_kernel(const float* __restrict__ tar, const float* __restrict__ src,
                               float* __restrict__ out) {
    const int t = threadIdx.x;
    float acc = 0.f;
    #pragma unroll
    for (int u = 0; u < 2; u++) {
        const int fq  = blockIdx.x * 512 + u * 256 + t;   // flat query id
        const int dir = fq >> 15;                          // 32768 queries per dir
        const int rem = fq & 32767;                        // b*NPTS + qi
        const float* qraw = (dir == 0) ? tar : src;
        const float* qp = qraw + (size_t)rem * 3;
        const float x = qp[0], y = qp[1], z = qp[2];
        const float qn = fmaf(x, x, fmaf(y, y, z * z));

        float m = g_pmin[0][fq];
        #pragma unroll
        for (int s = 1; s < SPLITS; s++) m = fminf(m, g_pmin[s][fq]);
        acc += sqrtf(fmaxf(qn + m, 0.f));
    }

    #pragma unroll
    for (int o = 16; o > 0; o >>= 1)
        acc += __shfl_down_sync(0xffffffffu, acc, o);

    __shared__ float ws[8];
    __shared__ int is_last;
    if ((t & 31) == 0) ws[t >> 5] = acc;
    __syncthreads();
    if (t == 0) {
        float sblk = 0.f;
        #pragma unroll
        for (int i = 0; i < 8; i++) sblk += ws[i];
        g_bpart[blockIdx.x] = sblk;   // blocks [0,64) = dir0, [64,128) = dir1
        __threadfence();
        is_last = (atomicAdd(&g_count, 1) == CGRID - 1);
    }
    __syncthreads();

    if (is_last) {
        __threadfence();  // acquire: make all g_bpart writes visible
        float v = (t < CGRID) ? g_bpart[t] : 0.f;
        #pragma unroll
        for (int o = 16; o > 0; o >>= 1)
            v += __shfl_down_sync(0xffffffffu, v, o);
        if ((t & 31) == 0) ws[t >> 5] = v;
        __syncthreads();
        if (t == 0) {
            const float inv = 1.f / (float)(BATCH * NPTS);
            float complete = (ws[0] + ws[1]) * inv;   // dir 0 (tar -> src)
            float accuracy = (ws[2] + ws[3]) * inv;   // dir 1 (src -> tar)
            out[0] = accuracy;
            out[1] = complete;
            out[2] = 0.5f * (accuracy + complete);
            g_count = 0;   // reset for next graph replay (deterministic)
        }
    }
}

extern "C" void kernel_launch(void* const* d_in, const int* in_sizes, int n_in,
                              void* d_out, int out_size) {
    const float* tar = (const float*)d_in[0];
    const float* src = (const float*)d_in[1];
    float* out = (float*)d_out;

    chamfer_kernel<<<dim3(QTILES * SPLITS, BATCH, 2), TPB>>>(tar, src);
    combine_kernel<<<CGRID, 256>>>(tar, src, out);
}